// round 9
// baseline (speedup 1.0000x reference)
#include <cuda_runtime.h>
#include <cuda_bf16.h>
#include <math.h>

// Problem constants
#define BB   4
#define SS   1024
#define DIN  256
#define VV   256
#define KDIM 64
#define HH   8
#define TT   4
#define BS   (BB*SS)          // 4096
#define NCH  32               // stat chunks per head
#define EPS  1e-3f

// ---------------- scratch (device globals; no allocation allowed) -----------
__device__ float g_net[HH*BS*VV];            // raw layer input / y2
__device__ float g_y1[HH*BS*VV];             // raw post-attention
__device__ float g_q[HH*BS*KDIM];
__device__ float g_k[HH*BS*KDIM];
__device__ float g_v[HH*BS*VV];
__device__ float g_scores[(size_t)HH*BB*SS*SS];  // 134MB
__device__ float g_part[HH*NCH*VV*2];
__device__ float g_affA[HH*2*VV];            // affine for g_net   [h][sc|sh][c]
__device__ float g_affB[HH*2*VV];            // affine for g_y1

// ---------------- TF32 helpers ----------------------------------------------
__device__ __forceinline__ unsigned f2tf(float f) {
    unsigned r;
    asm("cvt.rna.tf32.f32 %0, %1;" : "=r"(r) : "f"(f));
    return r;
}

__device__ __forceinline__ void split_tf32(float f, unsigned &hi, unsigned &lo) {
    hi = f2tf(f);
    lo = f2tf(f - __uint_as_float(hi));
}

__device__ __forceinline__ void mma_tf32(float c[4],
                                         const unsigned a[4],
                                         const unsigned b[2]) {
    asm volatile(
        "mma.sync.aligned.m16n8k8.row.col.f32.tf32.tf32.f32 "
        "{%0,%1,%2,%3}, {%4,%5,%6,%7}, {%8,%9}, {%0,%1,%2,%3};"
        : "+f"(c[0]), "+f"(c[1]), "+f"(c[2]), "+f"(c[3])
        : "r"(a[0]), "r"(a[1]), "r"(a[2]), "r"(a[3]), "r"(b[0]), "r"(b[1]));
}

// ---------------- 3xTF32 tensor-core GEMM core -------------------------------
#define GBM 128
#define GBN 64
#define GBK 32
#define ASTR 36
#define BSTR_NN 72
#define BSTR_NT 36
#define A_TILE (GBM*ASTR)
#define B_TILE 2304
#define SMEM_U32 (2*A_TILE + 2*B_TILE)      // 13824 u32
#define SMEM_TOT (SMEM_U32 + 512)           // + affine coef slots

// EPI: 0 = plain C=alpha*acc (with rep)
//      1 = attnout fuse: y=affR(R)+acc, C=y, stats (h=z>>2, chunk=(z&3)*8+by)
//      2 = Wd fuse:      y=affR(R)+relu(acc), C=y, stats (h=z, chunk=by)
// AFFA: apply per-column affine to A during load (affA, indexed by h=blockIdx.z)
template<int NT, int EPI, int AFFA>
__global__ void __launch_bounds__(256)
gemm_mma(const float* __restrict__ A, const float* __restrict__ B,
         float* __restrict__ C, const float* __restrict__ R,
         float* __restrict__ part,
         const float* __restrict__ affA, const float* __restrict__ affR,
         int M, int N, int K,
         long long sA, long long sB, long long sC, long long sR,
         float alpha, int rep, long long repStride)
{
    A += (long long)blockIdx.z * sA;
    B += (long long)blockIdx.z * sB;
    C += (long long)blockIdx.z * sC;
    if (EPI) R += (long long)blockIdx.z * sR;

    extern __shared__ unsigned smem[];
    unsigned* AsH = smem;
    unsigned* AsL = smem + A_TILE;
    unsigned* BsH = smem + 2*A_TILE;
    unsigned* BsL = smem + 2*A_TILE + B_TILE;
    float* scS = (float*)(smem + SMEM_U32);
    float* shS = scS + 256;

    const int t    = threadIdx.x;
    const int lane = t & 31;
    const int wid  = t >> 5;
    const int gid  = lane >> 2;
    const int tig  = lane & 3;
    const int wm   = (wid & 3) * 32;
    const int wn   = (wid >> 2) * 32;
    const int m0 = blockIdx.y * GBM, n0 = blockIdx.x * GBN;

    if (AFFA) {
        const float* ab = affA + (size_t)blockIdx.z * 2 * VV;
        scS[t] = ab[t];
        shS[t] = ab[VV + t];
        __syncthreads();
    }

    float acc[2][4][4] = {};

    for (int k0 = 0; k0 < K; k0 += GBK) {
        float4 ar[4];
        #pragma unroll
        for (int i = 0; i < 4; i++) {
            int idx = t + i * 256;
            int r = idx >> 3, c4 = (idx & 7) << 2;
            ar[i] = *(const float4*)&A[(size_t)(m0 + r) * K + k0 + c4];
            if (AFFA) {
                int cc = k0 + c4;
                ar[i].x = fmaf(ar[i].x, scS[cc+0], shS[cc+0]);
                ar[i].y = fmaf(ar[i].y, scS[cc+1], shS[cc+1]);
                ar[i].z = fmaf(ar[i].z, scS[cc+2], shS[cc+2]);
                ar[i].w = fmaf(ar[i].w, scS[cc+3], shS[cc+3]);
            }
        }
        float4 br[2];
        #pragma unroll
        for (int i = 0; i < 2; i++) {
            int idx = t + i * 256;
            if (NT) {
                int r = idx >> 3, c4 = (idx & 7) << 2;
                br[i] = *(const float4*)&B[(size_t)(n0 + r) * K + k0 + c4];
            } else {
                int r = idx >> 4, c4 = (idx & 15) << 2;
                br[i] = *(const float4*)&B[(size_t)(k0 + r) * N + n0 + c4];
            }
        }
        __syncthreads();
        #pragma unroll
        for (int i = 0; i < 4; i++) {
            int idx = t + i * 256;
            int r = idx >> 3, c4 = (idx & 7) << 2;
            unsigned* ph = &AsH[r * ASTR + c4];
            unsigned* pl = &AsL[r * ASTR + c4];
            split_tf32(ar[i].x, ph[0], pl[0]);
            split_tf32(ar[i].y, ph[1], pl[1]);
            split_tf32(ar[i].z, ph[2], pl[2]);
            split_tf32(ar[i].w, ph[3], pl[3]);
        }
        #pragma unroll
        for (int i = 0; i < 2; i++) {
            int idx = t + i * 256;
            int off;
            if (NT) { int r = idx >> 3, c4 = (idx & 7) << 2;  off = r * BSTR_NT + c4; }
            else    { int r = idx >> 4, c4 = (idx & 15) << 2; off = r * BSTR_NN + c4; }
            unsigned* ph = &BsH[off];
            unsigned* pl = &BsL[off];
            split_tf32(br[i].x, ph[0], pl[0]);
            split_tf32(br[i].y, ph[1], pl[1]);
            split_tf32(br[i].z, ph[2], pl[2]);
            split_tf32(br[i].w, ph[3], pl[3]);
        }
        __syncthreads();

        #pragma unroll
        for (int ks = 0; ks < 4; ks++) {
            const int kk = ks * 8;
            unsigned aH[2][4], aL[2][4];
            #pragma unroll
            for (int i = 0; i < 2; i++) {
                const int mr = wm + i * 16;
                const int o0 = (mr + gid    ) * ASTR + kk + tig;
                const int o1 = (mr + gid + 8) * ASTR + kk + tig;
                aH[i][0] = AsH[o0];     aL[i][0] = AsL[o0];
                aH[i][1] = AsH[o1];     aL[i][1] = AsL[o1];
                aH[i][2] = AsH[o0 + 4]; aL[i][2] = AsL[o0 + 4];
                aH[i][3] = AsH[o1 + 4]; aL[i][3] = AsL[o1 + 4];
            }
            unsigned bH[4][2], bL[4][2];
            #pragma unroll
            for (int j = 0; j < 4; j++) {
                const int nc = wn + j * 8 + gid;
                int o0, o1;
                if (NT) { o0 = nc * BSTR_NT + kk + tig;  o1 = o0 + 4; }
                else    { o0 = (kk + tig) * BSTR_NN + nc; o1 = o0 + 4 * BSTR_NN; }
                bH[j][0] = BsH[o0]; bL[j][0] = BsL[o0];
                bH[j][1] = BsH[o1]; bL[j][1] = BsL[o1];
            }
            #pragma unroll
            for (int i = 0; i < 2; i++)
                #pragma unroll
                for (int j = 0; j < 4; j++) {
                    mma_tf32(acc[i][j], aL[i], bH[j]);
                    mma_tf32(acc[i][j], aH[i], bL[j]);
                    mma_tf32(acc[i][j], aH[i], bH[j]);
                }
        }
        __syncthreads();
    }

    if (EPI == 0) {
        #pragma unroll
        for (int i = 0; i < 2; i++)
            #pragma unroll
            for (int j = 0; j < 4; j++) {
                const int r0 = m0 + wm + i * 16 + gid;
                const int c0 = n0 + wn + j * 8 + tig * 2;
                float2 v01 = make_float2(acc[i][j][0] * alpha, acc[i][j][1] * alpha);
                float2 v23 = make_float2(acc[i][j][2] * alpha, acc[i][j][3] * alpha);
                for (int r = 0; r < rep; r++) {
                    *(float2*)&C[(size_t)r0 * N + c0 + (size_t)r * repStride] = v01;
                    *(float2*)&C[(size_t)(r0 + 8) * N + c0 + (size_t)r * repStride] = v23;
                }
            }
    } else {
        // y = affR(R) + (relu?)(acc); C = y; per-block column stats -> part
        const int hh = (EPI == 1) ? (blockIdx.z >> 2) : blockIdx.z;
        const float* affRh = affR + (size_t)hh * 2 * VV;
        float colsum[8] = {}, colsq[8] = {};
        #pragma unroll
        for (int i = 0; i < 2; i++)
            #pragma unroll
            for (int j = 0; j < 4; j++) {
                const int r0 = m0 + wm + i * 16 + gid;
                const int c0 = n0 + wn + j * 8 + tig * 2;
                float2 sc2 = *(const float2*)&affRh[c0];
                float2 sh2 = *(const float2*)&affRh[VV + c0];
                float2 a0 = *(const float2*)&R[(size_t)r0 * N + c0];
                float2 a1 = *(const float2*)&R[(size_t)(r0 + 8) * N + c0];
                float v0 = acc[i][j][0], v1 = acc[i][j][1];
                float v2 = acc[i][j][2], v3 = acc[i][j][3];
                if (EPI == 2) {
                    v0 = fmaxf(v0, 0.f); v1 = fmaxf(v1, 0.f);
                    v2 = fmaxf(v2, 0.f); v3 = fmaxf(v3, 0.f);
                }
                float y00 = fmaf(a0.x, sc2.x, sh2.x) + v0;
                float y01 = fmaf(a0.y, sc2.y, sh2.y) + v1;
                float y10 = fmaf(a1.x, sc2.x, sh2.x) + v2;
                float y11 = fmaf(a1.y, sc2.y, sh2.y) + v3;
                *(float2*)&C[(size_t)r0 * N + c0]       = make_float2(y00, y01);
                *(float2*)&C[(size_t)(r0 + 8) * N + c0] = make_float2(y10, y11);
                colsum[j*2+0] += y00 + y10;
                colsum[j*2+1] += y01 + y11;
                colsq [j*2+0] += y00*y00 + y10*y10;
                colsq [j*2+1] += y01*y01 + y11*y11;
            }
        #pragma unroll
        for (int c8 = 0; c8 < 8; c8++) {
            #pragma unroll
            for (int msk = 4; msk <= 16; msk <<= 1) {
                colsum[c8] += __shfl_xor_sync(0xffffffffu, colsum[c8], msk);
                colsq [c8] += __shfl_xor_sync(0xffffffffu, colsq [c8], msk);
            }
        }
        float* sred = (float*)smem;   // [4 m-warps][64 cols][2]
        __syncthreads();
        if (gid == 0) {
            #pragma unroll
            for (int j = 0; j < 4; j++)
                #pragma unroll
                for (int e = 0; e < 2; e++) {
                    int col = wn + j * 8 + tig * 2 + e;
                    int idx = ((wid & 3) * 64 + col) * 2;
                    sred[idx + 0] = colsum[j*2+e];
                    sred[idx + 1] = colsq [j*2+e];
                }
        }
        __syncthreads();
        if (t < 64) {
            float s = 0.f, q2 = 0.f;
            #pragma unroll
            for (int w = 0; w < 4; w++) {
                s  += sred[(w * 64 + t) * 2 + 0];
                q2 += sred[(w * 64 + t) * 2 + 1];
            }
            int chunk = (EPI == 1) ? ((blockIdx.z & 3) * 8 + blockIdx.y) : blockIdx.y;
            size_t p = ((size_t)(hh * NCH + chunk) * VV + (n0 + t)) * 2;
            part[p + 0] = s;
            part[p + 1] = q2;
        }
    }
}

// ---------------- fused q/k/v projection (one launch, affine A) --------------
__global__ void __launch_bounds__(256)
gemm_qkv(const float* __restrict__ net,
         const float* __restrict__ Wq_t, const float* __restrict__ Wk_t,
         const float* __restrict__ Wv_t,
         float* __restrict__ q, float* __restrict__ k, float* __restrict__ v,
         const float* __restrict__ aff)
{
    const int h = blockIdx.z;
    const int bx = blockIdx.x;
    const float* A = net + (size_t)h * BS * VV;
    const float* B;
    float* C;
    int N, n0;
    if (bx == 0)      { B = Wq_t + (size_t)h * TT * VV * KDIM; C = q + (size_t)h * BS * KDIM; N = KDIM; n0 = 0; }
    else if (bx == 1) { B = Wk_t + (size_t)h * TT * VV * KDIM; C = k + (size_t)h * BS * KDIM; N = KDIM; n0 = 0; }
    else              { B = Wv_t + (size_t)h * TT * VV * VV;   C = v + (size_t)h * BS * VV;   N = VV;   n0 = (bx - 2) * GBN; }
    const int K = VV;

    extern __shared__ unsigned smem[];
    unsigned* AsH = smem;
    unsigned* AsL = smem + A_TILE;
    unsigned* BsH = smem + 2*A_TILE;
    unsigned* BsL = smem + 2*A_TILE + B_TILE;
    float* scS = (float*)(smem + SMEM_U32);
    float* shS = scS + 256;

    const int t    = threadIdx.x;
    const int lane = t & 31;
    const int wid  = t >> 5;
    const int gid  = lane >> 2;
    const int tig  = lane & 3;
    const int wm   = (wid & 3) * 32;
    const int wn   = (wid >> 2) * 32;
    const int m0 = blockIdx.y * GBM;

    {
        const float* ab = aff + (size_t)h * 2 * VV;
        scS[t] = ab[t];
        shS[t] = ab[VV + t];
        __syncthreads();
    }

    float acc[2][4][4] = {};

    for (int k0 = 0; k0 < K; k0 += GBK) {
        float4 ar[4];
        #pragma unroll
        for (int i = 0; i < 4; i++) {
            int idx = t + i * 256;
            int r = idx >> 3, c4 = (idx & 7) << 2;
            ar[i] = *(const float4*)&A[(size_t)(m0 + r) * K + k0 + c4];
            int cc = k0 + c4;
            ar[i].x = fmaf(ar[i].x, scS[cc+0], shS[cc+0]);
            ar[i].y = fmaf(ar[i].y, scS[cc+1], shS[cc+1]);
            ar[i].z = fmaf(ar[i].z, scS[cc+2], shS[cc+2]);
            ar[i].w = fmaf(ar[i].w, scS[cc+3], shS[cc+3]);
        }
        float4 br[2];
        #pragma unroll
        for (int i = 0; i < 2; i++) {
            int idx = t + i * 256;
            int r = idx >> 4, c4 = (idx & 15) << 2;
            br[i] = *(const float4*)&B[(size_t)(k0 + r) * N + n0 + c4];
        }
        __syncthreads();
        #pragma unroll
        for (int i = 0; i < 4; i++) {
            int idx = t + i * 256;
            int r = idx >> 3, c4 = (idx & 7) << 2;
            unsigned* ph = &AsH[r * ASTR + c4];
            unsigned* pl = &AsL[r * ASTR + c4];
            split_tf32(ar[i].x, ph[0], pl[0]);
            split_tf32(ar[i].y, ph[1], pl[1]);
            split_tf32(ar[i].z, ph[2], pl[2]);
            split_tf32(ar[i].w, ph[3], pl[3]);
        }
        #pragma unroll
        for (int i = 0; i < 2; i++) {
            int idx = t + i * 256;
            int r = idx >> 4, c4 = (idx & 15) << 2;
            int off = r * BSTR_NN + c4;
            unsigned* ph = &BsH[off];
            unsigned* pl = &BsL[off];
            split_tf32(br[i].x, ph[0], pl[0]);
            split_tf32(br[i].y, ph[1], pl[1]);
            split_tf32(br[i].z, ph[2], pl[2]);
            split_tf32(br[i].w, ph[3], pl[3]);
        }
        __syncthreads();

        #pragma unroll
        for (int ks = 0; ks < 4; ks++) {
            const int kk = ks * 8;
            unsigned aH[2][4], aL[2][4];
            #pragma unroll
            for (int i = 0; i < 2; i++) {
                const int mr = wm + i * 16;
                const int o0 = (mr + gid    ) * ASTR + kk + tig;
                const int o1 = (mr + gid + 8) * ASTR + kk + tig;
                aH[i][0] = AsH[o0];     aL[i][0] = AsL[o0];
                aH[i][1] = AsH[o1];     aL[i][1] = AsL[o1];
                aH[i][2] = AsH[o0 + 4]; aL[i][2] = AsL[o0 + 4];
                aH[i][3] = AsH[o1 + 4]; aL[i][3] = AsL[o1 + 4];
            }
            unsigned bH[4][2], bL[4][2];
            #pragma unroll
            for (int j = 0; j < 4; j++) {
                const int nc = wn + j * 8 + gid;
                int o0 = (kk + tig) * BSTR_NN + nc;
                int o1 = o0 + 4 * BSTR_NN;
                bH[j][0] = BsH[o0]; bL[j][0] = BsL[o0];
                bH[j][1] = BsH[o1]; bL[j][1] = BsL[o1];
            }
            #pragma unroll
            for (int i = 0; i < 2; i++)
                #pragma unroll
                for (int j = 0; j < 4; j++) {
                    mma_tf32(acc[i][j], aL[i], bH[j]);
                    mma_tf32(acc[i][j], aH[i], bL[j]);
                    mma_tf32(acc[i][j], aH[i], bH[j]);
                }
        }
        __syncthreads();
    }

    #pragma unroll
    for (int i = 0; i < 2; i++)
        #pragma unroll
        for (int j = 0; j < 4; j++) {
            const int r0 = m0 + wm + i * 16 + gid;
            const int c0 = n0 + wn + j * 8 + tig * 2;
            *(float2*)&C[(size_t)r0 * N + c0] =
                make_float2(acc[i][j][0], acc[i][j][1]);
            *(float2*)&C[(size_t)(r0 + 8) * N + c0] =
                make_float2(acc[i][j][2], acc[i][j][3]);
        }
}

// ---------------- softmax over rows of length 1024 ---------------------------
__global__ void softmax_rows(float* __restrict__ s)
{
    float* row = s + (size_t)blockIdx.x * SS;
    const int tid = threadIdx.x;
    __shared__ float red[256];
    float v[4];
    float m = -1e30f;
    #pragma unroll
    for (int i = 0; i < 4; i++) { v[i] = row[tid + i*256]; m = fmaxf(m, v[i]); }
    red[tid] = m; __syncthreads();
    for (int st = 128; st > 0; st >>= 1) {
        if (tid < st) red[tid] = fmaxf(red[tid], red[tid + st]);
        __syncthreads();
    }
    m = red[0]; __syncthreads();
    float sum = 0.f;
    #pragma unroll
    for (int i = 0; i < 4; i++) { v[i] = __expf(v[i] - m); sum += v[i]; }
    red[tid] = sum; __syncthreads();
    for (int st = 128; st > 0; st >>= 1) {
        if (tid < st) red[tid] += red[tid + st];
        __syncthreads();
    }
    const float inv = 1.f / red[0];
    #pragma unroll
    for (int i = 0; i < 4; i++) row[tid + i*256] = v[i] * inv;
}

// ---------------- BN stats -> affine coefficients ----------------------------
__global__ void bn_stats(const float* __restrict__ part,
                         const float* __restrict__ gamma, const float* __restrict__ beta,
                         float* __restrict__ aff, int gstride)
{
    const int c = threadIdx.x;
    const int h = blockIdx.x;
    const float* p = part + (size_t)h * NCH * VV * 2;
    float sum = 0.f, sq = 0.f;
    #pragma unroll
    for (int j = 0; j < NCH; j++) {
        sum += p[((size_t)j*VV + c)*2 + 0];
        sq  += p[((size_t)j*VV + c)*2 + 1];
    }
    const float mean = sum * (1.f / BS);
    const float var  = sq  * (1.f / BS) - mean * mean;
    const float inv  = rsqrtf(var + EPS);
    const float g = gamma[(size_t)h * gstride + c];
    const float b = beta [(size_t)h * gstride + c];
    const float sc = inv * g;
    aff[(size_t)h * 2 * VV + c]      = sc;
    aff[(size_t)h * 2 * VV + VV + c] = b - mean * sc;
}

// ---------------- init affine to identity ------------------------------------
__global__ void init_aff(float* __restrict__ aff)
{
    const int c = threadIdx.x, h = blockIdx.x;
    aff[(size_t)h * 2 * VV + c]      = 1.f;
    aff[(size_t)h * 2 * VV + VV + c] = 0.f;
}

// ---------------- final: affine + [H][B*S][V] -> [B,S,H,V] -------------------
__global__ void out_norm(const float* __restrict__ net, const float* __restrict__ aff,
                         float* __restrict__ out)
{
    const int h = blockIdx.y, row = blockIdx.x, c = threadIdx.x;
    const float sc = aff[(size_t)h * 2 * VV + c];
    const float sh = aff[(size_t)h * 2 * VV + VV + c];
    out[((size_t)row * HH + h) * VV + c] =
        fmaf(net[(size_t)h * BS * VV + (size_t)row * VV + c], sc, sh);
}

// ---------------- launcher ---------------------------------------------------
extern "C" void kernel_launch(void* const* d_in, const int* in_sizes, int n_in,
                              void* d_out, int out_size)
{
    const float* x     = (const float*)d_in[0];
    const float* W_in  = (const float*)d_in[1];
    const float* Wq    = (const float*)d_in[2];
    const float* Wk    = (const float*)d_in[3];
    const float* Wv    = (const float*)d_in[4];
    const float* Wd    = (const float*)d_in[5];
    const float* g1    = (const float*)d_in[6];
    const float* b1    = (const float*)d_in[7];
    const float* g2    = (const float*)d_in[8];
    const float* b2    = (const float*)d_in[9];
    float* out = (float*)d_out;

    float *net, *y1, *q, *k, *v, *scores, *part, *affA, *affB;
    cudaGetSymbolAddress((void**)&net,    g_net);
    cudaGetSymbolAddress((void**)&y1,     g_y1);
    cudaGetSymbolAddress((void**)&q,      g_q);
    cudaGetSymbolAddress((void**)&k,      g_k);
    cudaGetSymbolAddress((void**)&v,      g_v);
    cudaGetSymbolAddress((void**)&scores, g_scores);
    cudaGetSymbolAddress((void**)&part,   g_part);
    cudaGetSymbolAddress((void**)&affA,   g_affA);
    cudaGetSymbolAddress((void**)&affB,   g_affB);

    const int smem_bytes = SMEM_TOT * 4;   // 57344
    static int configured = 0;
    if (!configured) {
        cudaFuncSetAttribute(gemm_mma<0,0,0>, cudaFuncAttributeMaxDynamicSharedMemorySize, smem_bytes);
        cudaFuncSetAttribute(gemm_mma<1,0,0>, cudaFuncAttributeMaxDynamicSharedMemorySize, smem_bytes);
        cudaFuncSetAttribute(gemm_mma<0,1,0>, cudaFuncAttributeMaxDynamicSharedMemorySize, smem_bytes);
        cudaFuncSetAttribute(gemm_mma<0,2,1>, cudaFuncAttributeMaxDynamicSharedMemorySize, smem_bytes);
        cudaFuncSetAttribute(gemm_qkv,        cudaFuncAttributeMaxDynamicSharedMemorySize, smem_bytes);
        configured = 1;
    }

    const float scale = 0.125f;   // KD^-0.5

    // affine for layer-0 input = identity
    init_aff<<<HH, 256>>>(affA);

    // net[h] = x @ W_in (raw), replicated to all 8 heads
    gemm_mma<0,0,0><<<dim3(VV/GBN, BS/GBM, 1), 256, smem_bytes>>>(
        x, W_in, net, nullptr, nullptr, nullptr, nullptr, BS, VV, DIN,
        0, 0, 0, 0, 1.f, HH, (long long)BS*VV);

    for (int t = 0; t < TT; t++) {
        // q, k, v in one launch, affine(affA) applied to net on load
        gemm_qkv<<<dim3(6, BS/GBM, HH), 256, smem_bytes>>>(
            net, Wq + (size_t)t*VV*KDIM, Wk + (size_t)t*VV*KDIM,
            Wv + (size_t)t*VV*VV, q, k, v, affA);

        // scores = scale * q @ k^T
        gemm_mma<1,0,0><<<dim3(SS/GBN, SS/GBM, HH*BB), 256, smem_bytes>>>(
            q, k, scores, nullptr, nullptr, nullptr, nullptr, SS, SS, KDIM,
            (long long)SS*KDIM, (long long)SS*KDIM, (long long)SS*SS, 0,
            scale, 1, 0);

        softmax_rows<<<HH*BB*SS, 256>>>(scores);

        // y1 = affA(net) + scores @ v, stats -> part
        gemm_mma<0,1,0><<<dim3(VV/GBN, SS/GBM, HH*BB), 256, smem_bytes>>>(
            scores, v, y1, net, part, nullptr, affA, SS, VV, SS,
            (long long)SS*SS, (long long)SS*VV, (long long)SS*VV, (long long)SS*VV,
            1.f, 1, 0);
        bn_stats<<<HH, 256>>>(part, g1 + (size_t)t*VV, b1 + (size_t)t*VV, affB, TT*VV);

        // net(y2) = affB(y1) + relu(affB(y1) @ Wd), stats -> part
        gemm_mma<0,2,1><<<dim3(VV/GBN, BS/GBM, HH), 256, smem_bytes>>>(
            y1, Wd + (size_t)t*VV*VV, net, y1, part, affB, affB, BS, VV, VV,
            (long long)BS*VV, (long long)TT*VV*VV, (long long)BS*VV, (long long)BS*VV,
            1.f, 1, 0);
        bn_stats<<<HH, 256>>>(part, g2 + (size_t)t*VV, b2 + (size_t)t*VV, affA, TT*VV);
    }

    out_norm<<<dim3(BS, HH), 256>>>(net, affA, out);
}